// round 12
// baseline (speedup 1.0000x reference)
#include <cuda_runtime.h>
#include <cuda_bf16.h>
#include <cstdint>

#define NN 50000
#define NE 500000
#define DD 128
#define BN_EPS_F 1e-5f
#define NBLK_SCAN 196
#define NTILE 782              // ceil(50000/64)
#define GRID_P 296             // 148 SMs x 2 CTA -> all-resident persistent grid
#define NPB 169                // ceil(50000/296) gather nodes per block

// smem layout (bytes)
#define SM_AHI 0
#define SM_ALO 17408
#define SM_BHI 34816
#define SM_BLO 69632
#define SM_BIAS 104448         // bias(128)+rbias(128)
#define SM_BN   105472         // scale(128)+shift(128)
#define SM_PS   106496         // 2 x 128 floats
#define SM_QS   107520         // 2 x 128 floats
#define TC_SMEM 108544

// ---------------- device scratch ----------------
__device__ __align__(16) float g_ha[NN * DD];
__device__ __align__(16) float g_hb[NN * DD];
__device__ __align__(16) float g_agg[NN * DD];
__device__ float g_out_norm[NN];
__device__ float g_in_norm[NN];
__device__ int   g_deg[2 * NN];
__device__ int   g_rowptr[NN + 1];
__device__ int   g_fill[NN];
__device__ int   g_col[NE];
__device__ int   g_blk[256];
__device__ float g_stats[3 * 256];       // per-layer sum/sumsq buffers
__device__ unsigned g_barcnt;
// padded bf16 weight images: [layer][z][ hi 34816B | lo 34816B ], Bt[n][k] 136-half rows
__device__ __align__(16) char g_wimg[6 * 69632];

// ---------------- helpers ----------------
__device__ __forceinline__ float relu(float x) { return fmaxf(x, 0.f); }
__device__ __forceinline__ uint32_t bfpair(float x, float y) {
    __nv_bfloat162 t = __floats2bfloat162_rn(x, y);
    return *reinterpret_cast<uint32_t*>(&t);
}
__device__ __forceinline__ uint32_t smem_u32(const void* p) {
    uint32_t a;
    asm("{ .reg .u64 t; cvta.to.shared.u64 t, %1; cvt.u32.u64 %0, t; }" : "=r"(a) : "l"(p));
    return a;
}
#define MMA(d, a0, a1, a2, a3, b0, b1) \
    asm volatile("mma.sync.aligned.m16n8k16.row.col.f32.bf16.bf16.f32 " \
        "{%0,%1,%2,%3}, {%4,%5,%6,%7}, {%8,%9}, {%0,%1,%2,%3};" \
        : "+f"((d)[0]), "+f"((d)[1]), "+f"((d)[2]), "+f"((d)[3]) \
        : "r"(a0), "r"(a1), "r"(a2), "r"(a3), "r"(b0), "r"(b1))
#define LDSM4(r, a) \
    asm volatile("ldmatrix.sync.aligned.m8n8.x4.shared.b16 {%0,%1,%2,%3}, [%4];" \
        : "=r"((r)[0]), "=r"((r)[1]), "=r"((r)[2]), "=r"((r)[3]) : "r"(a))

__device__ __forceinline__ void grid_bar(unsigned target) {
    __syncthreads();
    if (threadIdx.x == 0) {
        __threadfence();
        atomicAdd(&g_barcnt, 1u);
        volatile unsigned* p = &g_barcnt;
        while (*p < target) { }
    }
    __syncthreads();
}

// ---------------- prep kernels ----------------
__global__ void init_deg_kernel() {
    int i = blockIdx.x * 256 + threadIdx.x;
    if (i < 2 * NN) g_deg[i] = 0;
    if (i < 3 * 256) g_stats[i] = 0.f;
    if (i == 0) g_barcnt = 0u;
}
__global__ void count_deg_kernel(const int* __restrict__ src, const int* __restrict__ dst) {
    int e = blockIdx.x * 256 + threadIdx.x;
    if (e < NE) { atomicAdd(&g_deg[src[e]], 1); atomicAdd(&g_deg[NN + dst[e]], 1); }
}
__global__ void norms_kernel() {
    int i = blockIdx.x * 256 + threadIdx.x;
    if (i < NN) {
        int d0 = g_deg[i], d1 = g_deg[NN + i];
        g_out_norm[i] = d0 > 0 ? rsqrtf((float)d0) : 0.f;
        g_in_norm[i]  = d1 > 0 ? rsqrtf((float)d1) : 0.f;
    }
}
__global__ void scanA_kernel() {
    __shared__ int s[256];
    int t = threadIdx.x, b = blockIdx.x, i = b * 256 + t;
    int d = (i < NN) ? g_deg[NN + i] : 0;
    s[t] = d; __syncthreads();
    #pragma unroll
    for (int off = 1; off < 256; off <<= 1) {
        int v = (t >= off) ? s[t - off] : 0; __syncthreads();
        s[t] += v; __syncthreads();
    }
    if (i < NN) g_rowptr[i] = s[t] - d;
    if (t == 255) g_blk[b] = s[255];
}
__global__ void scanB_kernel() {
    __shared__ int s[256];
    int t = threadIdx.x;
    int d = (t < NBLK_SCAN) ? g_blk[t] : 0;
    s[t] = d; __syncthreads();
    #pragma unroll
    for (int off = 1; off < 256; off <<= 1) {
        int v = (t >= off) ? s[t - off] : 0; __syncthreads();
        s[t] += v; __syncthreads();
    }
    g_blk[t] = s[t] - d;
}
__global__ void scanC_kernel() {
    int i = blockIdx.x * 256 + threadIdx.x;
    if (i < NN) { int rp = g_rowptr[i] + g_blk[i >> 8]; g_rowptr[i] = rp; g_fill[i] = rp; }
    if (i == 0) g_rowptr[NN] = NE;
}
__global__ void fill_kernel(const int* __restrict__ src, const int* __restrict__ dst) {
    int e = blockIdx.x * 256 + threadIdx.x;
    if (e < NE) g_col[atomicAdd(&g_fill[dst[e]], 1)] = src[e];
}
__global__ void embed_kernel(const int* __restrict__ node_ids, const float* __restrict__ emb) {
    int idx = blockIdx.x * 256 + threadIdx.x;
    int row = idx >> 5, c = idx & 31;
    reinterpret_cast<float4*>(g_ha)[idx] = reinterpret_cast<const float4*>(emb)[node_ids[row] * 32 + c];
}
__global__ void prep_weights(const float* __restrict__ Ws, const float* __restrict__ Rws) {
    int t = blockIdx.x * 256 + threadIdx.x;
    if (t >= 6 * 128 * 136) return;
    int kk = t % 136, r = t / 136;
    int n = r & 127; r >>= 7;
    int z = r & 1, l = r >> 1;
    float hi = 0.f, lo = 0.f;
    if (kk < 128) {
        float v = (z ? Rws : Ws)[l * 16384 + kk * 128 + n];
        __nv_bfloat16 h = __float2bfloat16(v);
        hi = __bfloat162float(h);
        lo = v - hi;
    }
    __nv_bfloat16* img = reinterpret_cast<__nv_bfloat16*>(g_wimg + (size_t)(l * 2 + z) * 69632);
    img[n * 136 + kk] = __float2bfloat16(hi);
    img[17408 + n * 136 + kk] = __float2bfloat16(lo);
}

// ---------------- persistent-kernel building blocks ----------------
__device__ __forceinline__ void stage_B(char* smc, int layer, int z, int tid) {
    const float4* wsrc = reinterpret_cast<const float4*>(g_wimg + (size_t)(layer * 2 + z) * 69632);
    float4* bdst = reinterpret_cast<float4*>(smc + SM_BHI);
    #pragma unroll
    for (int i = 0; i < 17; i++) bdst[tid + i * 256] = wsrc[tid + i * 256];
}

__device__ __forceinline__ void stage_A(char* smc, const float4* __restrict__ A4, int base,
                                        int tid, bool affine, const float* sbn) {
    #pragma unroll
    for (int i = 0; i < 8; i++) {
        int qq = tid + i * 256;                // 0..2047
        int m = qq >> 5, c = qq & 31;
        int gr = base + m;
        float4 v = make_float4(0.f, 0.f, 0.f, 0.f);
        if (gr < NN) {
            v = __ldcg(&A4[gr * 32 + c]);
            if (affine) {
                float4 sc = reinterpret_cast<const float4*>(sbn)[c];
                float4 sh = reinterpret_cast<const float4*>(sbn)[32 + c];
                v.x = fmaf(v.x, sc.x, sh.x); v.y = fmaf(v.y, sc.y, sh.y);
                v.z = fmaf(v.z, sc.z, sh.z); v.w = fmaf(v.w, sc.w, sh.w);
            }
        }
        float h0 = __bfloat162float(__float2bfloat16(v.x));
        float h1 = __bfloat162float(__float2bfloat16(v.y));
        float h2 = __bfloat162float(__float2bfloat16(v.z));
        float h3 = __bfloat162float(__float2bfloat16(v.w));
        char* pa = smc + SM_AHI + m * 272 + c * 8;
        *reinterpret_cast<uint2*>(pa) = make_uint2(bfpair(h0, h1), bfpair(h2, h3));
        *reinterpret_cast<uint2*>(pa + 17408) =
            make_uint2(bfpair(v.x - h0, v.y - h1), bfpair(v.z - h2, v.w - h3));
    }
}

__device__ __forceinline__ void mma_tile(uint32_t aBase, uint32_t bBase, float acc[2][4][4]) {
    #pragma unroll
    for (int f = 0; f < 2; f++)
        #pragma unroll
        for (int g = 0; g < 4; g++)
            #pragma unroll
            for (int e = 0; e < 4; e++) acc[f][g][e] = 0.f;
    #pragma unroll
    for (int ks = 0; ks < 8; ks++) {
        uint32_t ah[2][4], al[2][4], bh[2][4], bl[2][4];
        #pragma unroll
        for (int f = 0; f < 2; f++) {
            uint32_t a = aBase + f * 4352 + ks * 32;
            LDSM4(ah[f], a);
            LDSM4(al[f], a + 17408);
        }
        #pragma unroll
        for (int gp = 0; gp < 2; gp++) {
            uint32_t b = bBase + gp * 4352 + ks * 32;
            LDSM4(bh[gp], b);
            LDSM4(bl[gp], b + 34816);
        }
        #pragma unroll
        for (int f = 0; f < 2; f++)
            #pragma unroll
            for (int gp = 0; gp < 2; gp++)
                #pragma unroll
                for (int gs = 0; gs < 2; gs++) {
                    float* d = acc[f][2 * gp + gs];
                    MMA(d, ah[f][0], ah[f][1], ah[f][2], ah[f][3],
                        bh[gp][2 * gs], bh[gp][2 * gs + 1]);
                    MMA(d, ah[f][0], ah[f][1], ah[f][2], ah[f][3],
                        bl[gp][2 * gs], bl[gp][2 * gs + 1]);
                    MMA(d, al[f][0], al[f][1], al[f][2], al[f][3],
                        bh[gp][2 * gs], bh[gp][2 * gs + 1]);
                }
    }
}

// residual pass: OUT = relu(affine(IN) @ Rw + rb)
__device__ __forceinline__ void do_res(char* smc, uint32_t aBase, uint32_t bBase,
                                       const float4* IN4, float* OUT, int layer,
                                       int tid, int mw, int nw, int r, int q2,
                                       const float* sbias, const float* sbn) {
    stage_B(smc, layer, 1, tid);
    for (int tile = blockIdx.x; tile < NTILE; tile += GRID_P) {
        const int base = tile * 64;
        stage_A(smc, IN4, base, tid, true, sbn);
        __syncthreads();
        float acc[2][4][4];
        mma_tile(aBase, bBase, acc);
        #pragma unroll
        for (int f = 0; f < 2; f++)
            #pragma unroll
            for (int g = 0; g < 4; g++) {
                int row = mw * 32 + f * 16 + r;
                int col = nw * 32 + g * 8 + q2;
                float rb0 = sbias[128 + col], rb1 = sbias[128 + col + 1];
                int gr = base + row;
                if (gr < NN)
                    *reinterpret_cast<float2*>(&OUT[gr * DD + col]) =
                        make_float2(relu(acc[f][g][0] + rb0), relu(acc[f][g][1] + rb1));
                if (gr + 8 < NN)
                    *reinterpret_cast<float2*>(&OUT[(gr + 8) * DD + col]) =
                        make_float2(relu(acc[f][g][2] + rb0), relu(acc[f][g][3] + rb1));
            }
        __syncthreads();
    }
}

// gather: agg[d] = in_norm[d] * sum_{s in N(d)} out_norm[s] * affine(IN[s])
__device__ __forceinline__ void do_gather(const float4* __restrict__ IN4,
                                          int tid, const float* sbn) {
    int lane = tid & 31, wid = tid >> 5;
    int n0 = blockIdx.x * NPB;
    int n1 = n0 + NPB; if (n1 > NN) n1 = NN;
    float4 sc = reinterpret_cast<const float4*>(sbn)[lane];
    float4 sh = reinterpret_cast<const float4*>(sbn)[32 + lane];
    for (int nid = n0 + wid; nid < n1; nid += 8) {
        int j = g_rowptr[nid], end = g_rowptr[nid + 1];
        float4 acc = make_float4(0.f, 0.f, 0.f, 0.f);
        float nsum = 0.f;
        for (; j + 4 <= end; j += 4) {
            int s0 = g_col[j], s1 = g_col[j + 1], s2 = g_col[j + 2], s3 = g_col[j + 3];
            float n0_ = g_out_norm[s0], n1_ = g_out_norm[s1];
            float n2_ = g_out_norm[s2], n3_ = g_out_norm[s3];
            float4 v0 = __ldcg(&IN4[s0 * 32 + lane]), v1 = __ldcg(&IN4[s1 * 32 + lane]);
            float4 v2 = __ldcg(&IN4[s2 * 32 + lane]), v3 = __ldcg(&IN4[s3 * 32 + lane]);
            acc.x += n0_ * v0.x + n1_ * v1.x + n2_ * v2.x + n3_ * v3.x;
            acc.y += n0_ * v0.y + n1_ * v1.y + n2_ * v2.y + n3_ * v3.y;
            acc.z += n0_ * v0.z + n1_ * v1.z + n2_ * v2.z + n3_ * v3.z;
            acc.w += n0_ * v0.w + n1_ * v1.w + n2_ * v2.w + n3_ * v3.w;
            nsum += n0_ + n1_ + n2_ + n3_;
        }
        for (; j < end; j++) {
            int sN = g_col[j]; float on = g_out_norm[sN];
            float4 v = __ldcg(&IN4[sN * 32 + lane]);
            acc.x = fmaf(on, v.x, acc.x); acc.y = fmaf(on, v.y, acc.y);
            acc.z = fmaf(on, v.z, acc.z); acc.w = fmaf(on, v.w, acc.w);
            nsum += on;
        }
        float inr = g_in_norm[nid];
        float4 o;
        o.x = inr * fmaf(sc.x, acc.x, sh.x * nsum);
        o.y = inr * fmaf(sc.y, acc.y, sh.y * nsum);
        o.z = inr * fmaf(sc.z, acc.z, sh.z * nsum);
        o.w = inr * fmaf(sc.w, acc.w, sh.w * nsum);
        reinterpret_cast<float4*>(g_agg)[nid * 32 + lane] = o;
    }
}

// ---------------- the persistent layers kernel ----------------
__global__ void __launch_bounds__(256, 2)
layers_kernel(const float* __restrict__ bs, const float* __restrict__ Rbs,
              const float* __restrict__ gam, const float* __restrict__ bet,
              float* __restrict__ outp) {
    extern __shared__ char smc[];
    const uint32_t ub = smem_u32(smc);
    float* sbias = reinterpret_cast<float*>(smc + SM_BIAS);
    float* sbn   = reinterpret_cast<float*>(smc + SM_BN);
    float* ps    = reinterpret_cast<float*>(smc + SM_PS);
    float* qs    = reinterpret_cast<float*>(smc + SM_QS);

    const int tid = threadIdx.x, lane = tid & 31, wid = tid >> 5;
    const int mw = wid & 1, nw = wid >> 1;
    const int r = lane >> 2, q2 = (lane & 3) * 2;

    const uint32_t aBase = ub + SM_AHI
        + (uint32_t)(mw * 32 + (lane & 15)) * 272 + (uint32_t)(lane >> 4) * 16;
    const uint32_t bBase = ub + SM_BHI
        + (uint32_t)(nw * 32 + ((lane & 7) | ((lane >> 4) << 3))) * 272
        + (uint32_t)((lane >> 3) & 1) * 16;

    if (tid < 128) { sbn[tid] = 1.f; sbn[128 + tid] = 0.f; }   // identity BN for layer 0

    unsigned bar = 0;
    for (int l = 0; l < 3; l++) {
        const float4* IN4 = reinterpret_cast<const float4*>((l & 1) ? g_hb : g_ha);
        float* OUT = (l & 1) ? g_ha : g_hb;
        if (tid < 128) { sbias[tid] = bs[l * 128 + tid]; sbias[128 + tid] = Rbs[l * 128 + tid]; }
        __syncthreads();

        // ---- phase 1: residual GEMM + gather, parity-staggered for pipe overlap ----
        if (blockIdx.x & 1) {
            do_res(smc, aBase, bBase, IN4, OUT, l, tid, mw, nw, r, q2, sbias, sbn);
            do_gather(IN4, tid, sbn);
        } else {
            do_gather(IN4, tid, sbn);
            do_res(smc, aBase, bBase, IN4, OUT, l, tid, mw, nw, r, q2, sbias, sbn);
        }
        bar += GRID_P; grid_bar(bar);

        // ---- phase 2: conv GEMM (RMW add) + stats ----
        float s[8], sq[8];
        #pragma unroll
        for (int i = 0; i < 8; i++) { s[i] = 0.f; sq[i] = 0.f; }
        {
            const float4* A4 = reinterpret_cast<const float4*>(g_agg);
            stage_B(smc, l, 0, tid);
            for (int tile = blockIdx.x; tile < NTILE; tile += GRID_P) {
                const int base = tile * 64;
                stage_A(smc, A4, base, tid, false, sbn);
                __syncthreads();
                float acc[2][4][4];
                mma_tile(aBase, bBase, acc);
                #pragma unroll
                for (int f = 0; f < 2; f++)
                    #pragma unroll
                    for (int g = 0; g < 4; g++) {
                        int row = mw * 32 + f * 16 + r;
                        int col = nw * 32 + g * 8 + q2;
                        float b0 = sbias[col], b1 = sbias[col + 1];
                        int gr = base + row;
                        if (gr < NN) {
                            float2 c0 = __ldcg(reinterpret_cast<const float2*>(&OUT[gr * DD + col]));
                            float h0 = c0.x + relu(acc[f][g][0] + b0);
                            float h1 = c0.y + relu(acc[f][g][1] + b1);
                            *reinterpret_cast<float2*>(&OUT[gr * DD + col]) = make_float2(h0, h1);
                            s[g * 2] += h0; s[g * 2 + 1] += h1;
                            sq[g * 2] += h0 * h0; sq[g * 2 + 1] += h1 * h1;
                        }
                        if (gr + 8 < NN) {
                            float2 c1 = __ldcg(reinterpret_cast<const float2*>(&OUT[(gr + 8) * DD + col]));
                            float h2 = c1.x + relu(acc[f][g][2] + b0);
                            float h3 = c1.y + relu(acc[f][g][3] + b1);
                            *reinterpret_cast<float2*>(&OUT[(gr + 8) * DD + col]) = make_float2(h2, h3);
                            s[g * 2] += h2; s[g * 2 + 1] += h3;
                            sq[g * 2] += h2 * h2; sq[g * 2 + 1] += h3 * h3;
                        }
                    }
                __syncthreads();
            }
        }
        // block-level stats reduction -> g_stats[l]
        #pragma unroll
        for (int i = 0; i < 8; i++) {
            #pragma unroll
            for (int off = 4; off < 32; off <<= 1) {
                s[i]  += __shfl_xor_sync(0xffffffffu, s[i], off);
                sq[i] += __shfl_xor_sync(0xffffffffu, sq[i], off);
            }
        }
        if (lane < 4) {
            #pragma unroll
            for (int g = 0; g < 4; g++) {
                int col = nw * 32 + g * 8 + lane * 2;
                ps[mw * 128 + col]     = s[g * 2];
                ps[mw * 128 + col + 1] = s[g * 2 + 1];
                qs[mw * 128 + col]     = sq[g * 2];
                qs[mw * 128 + col + 1] = sq[g * 2 + 1];
            }
        }
        __syncthreads();
        if (tid < 128) {
            atomicAdd(&g_stats[l * 256 + tid], ps[tid] + ps[128 + tid]);
            atomicAdd(&g_stats[l * 256 + 128 + tid], qs[tid] + qs[128 + tid]);
        }
        bar += GRID_P; grid_bar(bar);

        // ---- every block computes BN params locally for the next consumer ----
        if (tid < 128) {
            float mu = __ldcg(&g_stats[l * 256 + tid]) * (1.f / NN);
            float var = fmaxf(__ldcg(&g_stats[l * 256 + 128 + tid]) * (1.f / NN) - mu * mu, 0.f);
            float inv = gam[l * 128 + tid] * rsqrtf(var + BN_EPS_F);
            sbn[tid] = inv;
            sbn[128 + tid] = bet[l * 128 + tid] - mu * inv;
        }
        __syncthreads();
    }

    // ---- final BN apply: out = g_hb * scale + shift ----
    const float4* H4 = reinterpret_cast<const float4*>(g_hb);
    float4* O4 = reinterpret_cast<float4*>(outp);
    for (int idx = blockIdx.x * 256 + tid; idx < NN * 32; idx += GRID_P * 256) {
        int c = idx & 31;
        float4 h = __ldcg(&H4[idx]);
        float4 sc = reinterpret_cast<const float4*>(sbn)[c];
        float4 sh = reinterpret_cast<const float4*>(sbn)[32 + c];
        float4 o;
        o.x = fmaf(h.x, sc.x, sh.x); o.y = fmaf(h.y, sc.y, sh.y);
        o.z = fmaf(h.z, sc.z, sh.z); o.w = fmaf(h.w, sc.w, sh.w);
        O4[idx] = o;
    }
}

// ---------------- launch ----------------
extern "C" void kernel_launch(void* const* d_in, const int* in_sizes, int n_in,
                              void* d_out, int out_size) {
    const int*   node_ids = (const int*)d_in[0];
    const int*   src      = (const int*)d_in[1];
    const int*   dst      = (const int*)d_in[2];
    const float* emb      = (const float*)d_in[3];
    const float* Ws       = (const float*)d_in[4];
    const float* bs       = (const float*)d_in[5];
    const float* Rws      = (const float*)d_in[6];
    const float* Rbs      = (const float*)d_in[7];
    const float* gam      = (const float*)d_in[8];
    const float* bet      = (const float*)d_in[9];
    float* outp = (float*)d_out;

    cudaFuncSetAttribute(layers_kernel, cudaFuncAttributeMaxDynamicSharedMemorySize, TC_SMEM);

    const int NV4 = NN * DD / 4;
    init_deg_kernel<<<(2 * NN + 255) / 256, 256>>>();
    count_deg_kernel<<<(NE + 255) / 256, 256>>>(src, dst);
    norms_kernel<<<(NN + 255) / 256, 256>>>();
    scanA_kernel<<<NBLK_SCAN, 256>>>();
    scanB_kernel<<<1, 256>>>();
    scanC_kernel<<<(NN + 255) / 256, 256>>>();
    fill_kernel<<<(NE + 255) / 256, 256>>>(src, dst);
    embed_kernel<<<NV4 / 256, 256>>>(node_ids, emb);
    prep_weights<<<(6 * 128 * 136 + 255) / 256, 256>>>(Ws, Rws);

    layers_kernel<<<GRID_P, 256, TC_SMEM>>>(bs, Rbs, gam, bet, outp);
}

// round 15
// speedup vs baseline: 1.1817x; 1.1817x over previous
#include <cuda_runtime.h>
#include <cuda_bf16.h>
#include <cstdint>

#define NN 50000
#define NE 500000
#define DD 128
#define BN_EPS_F 1e-5f
#define NBLK_SCAN 196
#define NTILE 782              // ceil(50000/64)
#define GRID_G 296             // 148 SMs x 2 CTAs -> single wave

// smem layout (bytes): 64-row A tiles, full 128-row B tiles, stride 272 B (136 halfs)
#define SM_AHI 0
#define SM_ALO 17408
#define SM_BHI 34816
#define SM_BLO 69632
#define SM_BIAS 104448         // 256 floats: bias | rbias
#define SM_PS   105472         // 2 x 128 floats
#define SM_QS   106496         // 2 x 128 floats
#define SM_BN   107520         // 256 floats: scale | shift
#define TC_SMEM 108544

// ---------------- device scratch ----------------
__device__ __align__(16) float g_ha[NN * DD];
__device__ __align__(16) float g_hb[NN * DD];
__device__ __align__(16) float g_agg[NN * DD];
__device__ float g_out_norm[NN];
__device__ float g_in_norm[NN];
__device__ int   g_deg[2 * NN];
__device__ int   g_rowptr[NN + 1];
__device__ int   g_fill[NN];
__device__ int   g_col[NE];
__device__ int   g_blk[256];
__device__ float g_stats[3 * 256];   // per-layer sum|sumsq
// padded bf16 weight images: [layer][z][ hi 34816B | lo 34816B ], Bt[n][k] 136-half rows
__device__ __align__(16) char g_wimg[6 * 69632];

// ---------------- helpers ----------------
__device__ __forceinline__ float relu(float x) { return fmaxf(x, 0.f); }
__device__ __forceinline__ uint32_t bfpair(float x, float y) {
    __nv_bfloat162 t = __floats2bfloat162_rn(x, y);
    return *reinterpret_cast<uint32_t*>(&t);
}
__device__ __forceinline__ uint32_t smem_u32(const void* p) {
    uint32_t a;
    asm("{ .reg .u64 t; cvta.to.shared.u64 t, %1; cvt.u32.u64 %0, t; }" : "=r"(a) : "l"(p));
    return a;
}
#define MMA(d, a0, a1, a2, a3, b0, b1) \
    asm volatile("mma.sync.aligned.m16n8k16.row.col.f32.bf16.bf16.f32 " \
        "{%0,%1,%2,%3}, {%4,%5,%6,%7}, {%8,%9}, {%0,%1,%2,%3};" \
        : "+f"((d)[0]), "+f"((d)[1]), "+f"((d)[2]), "+f"((d)[3]) \
        : "r"(a0), "r"(a1), "r"(a2), "r"(a3), "r"(b0), "r"(b1))
#define LDSM4(r, a) \
    asm volatile("ldmatrix.sync.aligned.m8n8.x4.shared.b16 {%0,%1,%2,%3}, [%4];" \
        : "=r"((r)[0]), "=r"((r)[1]), "=r"((r)[2]), "=r"((r)[3]) : "r"(a))

// compute BN scale/shift for "input of layer l" into sbn[256]; identity for l==0
__device__ __forceinline__ void compute_bn(float* sbn, int layer,
                                           const float* __restrict__ gam,
                                           const float* __restrict__ bet, int tid) {
    if (tid < 128) {
        if (layer == 0) {
            sbn[tid] = 1.f; sbn[128 + tid] = 0.f;
        } else {
            int pl = layer - 1;
            float mu = g_stats[pl * 256 + tid] * (1.f / NN);
            float var = fmaxf(g_stats[pl * 256 + 128 + tid] * (1.f / NN) - mu * mu, 0.f);
            float inv = gam[pl * 128 + tid] * rsqrtf(var + BN_EPS_F);
            sbn[tid] = inv;
            sbn[128 + tid] = bet[pl * 128 + tid] - mu * inv;
        }
    }
}

// ---------------- prep kernels ----------------
// merged: zero deg/stats + embed + weight split (all independent)
__global__ void prep0_kernel(const int* __restrict__ node_ids, const float* __restrict__ emb,
                             const float* __restrict__ Ws, const float* __restrict__ Rws) {
    int idx = blockIdx.x * 256 + threadIdx.x;
    if (idx < NN * 32) {               // embed
        int row = idx >> 5, c = idx & 31;
        reinterpret_cast<float4*>(g_ha)[idx] =
            reinterpret_cast<const float4*>(emb)[node_ids[row] * 32 + c];
    }
    if (idx < 2 * NN) g_deg[idx] = 0;
    if (idx < 3 * 256) g_stats[idx] = 0.f;
    if (idx < 6 * 128 * 136) {         // weight split + transpose + pad
        int kk = idx % 136, r = idx / 136;
        int n = r & 127; r >>= 7;
        int z = r & 1, l = r >> 1;
        float hi = 0.f, lo = 0.f;
        if (kk < 128) {
            float v = (z ? Rws : Ws)[l * 16384 + kk * 128 + n];
            __nv_bfloat16 h = __float2bfloat16(v);
            hi = __bfloat162float(h);
            lo = v - hi;
        }
        __nv_bfloat16* img = reinterpret_cast<__nv_bfloat16*>(g_wimg + (size_t)(l * 2 + z) * 69632);
        img[n * 136 + kk] = __float2bfloat16(hi);
        img[17408 + n * 136 + kk] = __float2bfloat16(lo);
    }
}
__global__ void count_deg_kernel(const int* __restrict__ src, const int* __restrict__ dst) {
    int e = blockIdx.x * 256 + threadIdx.x;
    if (e < NE) { atomicAdd(&g_deg[src[e]], 1); atomicAdd(&g_deg[NN + dst[e]], 1); }
}
// scanA + norms (both only need g_deg complete)
__global__ void scanA_kernel() {
    __shared__ int s[256];
    int t = threadIdx.x, b = blockIdx.x, i = b * 256 + t;
    int d = (i < NN) ? g_deg[NN + i] : 0;
    if (i < NN) {
        int d0 = g_deg[i];
        g_out_norm[i] = d0 > 0 ? rsqrtf((float)d0) : 0.f;
        g_in_norm[i]  = d > 0 ? rsqrtf((float)d) : 0.f;
    }
    s[t] = d; __syncthreads();
    #pragma unroll
    for (int off = 1; off < 256; off <<= 1) {
        int v = (t >= off) ? s[t - off] : 0; __syncthreads();
        s[t] += v; __syncthreads();
    }
    if (i < NN) g_rowptr[i] = s[t] - d;
    if (t == 255) g_blk[b] = s[255];
}
__global__ void scanB_kernel() {
    __shared__ int s[256];
    int t = threadIdx.x;
    int d = (t < NBLK_SCAN) ? g_blk[t] : 0;
    s[t] = d; __syncthreads();
    #pragma unroll
    for (int off = 1; off < 256; off <<= 1) {
        int v = (t >= off) ? s[t - off] : 0; __syncthreads();
        s[t] += v; __syncthreads();
    }
    g_blk[t] = s[t] - d;
}
__global__ void scanC_kernel() {
    int i = blockIdx.x * 256 + threadIdx.x;
    if (i < NN) { int rp = g_rowptr[i] + g_blk[i >> 8]; g_rowptr[i] = rp; g_fill[i] = rp; }
    if (i == 0) g_rowptr[NN] = NE;
}
__global__ void fill_kernel(const int* __restrict__ src, const int* __restrict__ dst) {
    int e = blockIdx.x * 256 + threadIdx.x;
    if (e < NE) g_col[atomicAdd(&g_fill[dst[e]], 1)] = src[e];
}

// ---------------- gather with locally-computed BN affine ----------------
__global__ void gather_kernel(const float* __restrict__ IN, int layer,
                              const float* __restrict__ gam, const float* __restrict__ bet) {
    __shared__ float sbn[256];
    int tid = threadIdx.x;
    compute_bn(sbn, layer, gam, bet, tid);
    __syncthreads();
    int nid = blockIdx.x * 8 + (tid >> 5);
    if (nid >= NN) return;
    int lane = tid & 31;
    int j = g_rowptr[nid], end = g_rowptr[nid + 1];
    const float4* x4 = reinterpret_cast<const float4*>(IN);
    float4 sc = reinterpret_cast<const float4*>(sbn)[lane];
    float4 sh = reinterpret_cast<const float4*>(sbn)[32 + lane];
    float4 acc = make_float4(0.f, 0.f, 0.f, 0.f);
    float nsum = 0.f;
    for (; j + 4 <= end; j += 4) {
        int s0 = g_col[j], s1 = g_col[j + 1], s2 = g_col[j + 2], s3 = g_col[j + 3];
        float n0 = g_out_norm[s0], n1 = g_out_norm[s1], n2 = g_out_norm[s2], n3 = g_out_norm[s3];
        float4 v0 = x4[s0 * 32 + lane], v1 = x4[s1 * 32 + lane];
        float4 v2 = x4[s2 * 32 + lane], v3 = x4[s3 * 32 + lane];
        acc.x += n0 * v0.x + n1 * v1.x + n2 * v2.x + n3 * v3.x;
        acc.y += n0 * v0.y + n1 * v1.y + n2 * v2.y + n3 * v3.y;
        acc.z += n0 * v0.z + n1 * v1.z + n2 * v2.z + n3 * v3.z;
        acc.w += n0 * v0.w + n1 * v1.w + n2 * v2.w + n3 * v3.w;
        nsum += n0 + n1 + n2 + n3;
    }
    for (; j < end; j++) {
        int s = g_col[j]; float on = g_out_norm[s];
        float4 v = x4[s * 32 + lane];
        acc.x = fmaf(on, v.x, acc.x); acc.y = fmaf(on, v.y, acc.y);
        acc.z = fmaf(on, v.z, acc.z); acc.w = fmaf(on, v.w, acc.w);
        nsum += on;
    }
    float inr = g_in_norm[nid];
    float4 o;
    o.x = inr * fmaf(sc.x, acc.x, sh.x * nsum);
    o.y = inr * fmaf(sc.y, acc.y, sh.y * nsum);
    o.z = inr * fmaf(sc.z, acc.z, sh.z * nsum);
    o.w = inr * fmaf(sc.w, acc.w, sh.w * nsum);
    reinterpret_cast<float4*>(g_agg)[nid * 32 + lane] = o;
}

// ---------------- HMMA dual GEMM: 1-wave grid, multi-tile per B load ----------------
__global__ void __launch_bounds__(256, 2)
gemm_kernel(const float* __restrict__ A0, const float* __restrict__ IN,
            float* __restrict__ OUT, int layer,
            const float* __restrict__ bvec, const float* __restrict__ rbvec,
            const float* __restrict__ gam, const float* __restrict__ bet) {
    extern __shared__ char smc[];
    const uint32_t ub = smem_u32(smc);
    float* sbias = reinterpret_cast<float*>(smc + SM_BIAS);
    float* ps    = reinterpret_cast<float*>(smc + SM_PS);
    float* qs    = reinterpret_cast<float*>(smc + SM_QS);
    float* sbn   = reinterpret_cast<float*>(smc + SM_BN);

    const int tid = threadIdx.x, lane = tid & 31, wid = tid >> 5;
    const int mw = wid & 1, nw = wid >> 1;       // 2 row-warps x 4 col-warps
    const int r = lane >> 2, q2 = (lane & 3) * 2;

    if (tid < 128) { sbias[tid] = bvec[tid]; sbias[128 + tid] = rbvec[tid]; }
    compute_bn(sbn, layer, gam, bet, tid);

    const uint32_t aBase = ub + SM_AHI
        + (uint32_t)(mw * 32 + (lane & 15)) * 272 + (uint32_t)(lane >> 4) * 16;
    const uint32_t bBase = ub + SM_BHI
        + (uint32_t)(nw * 32 + ((lane & 7) | ((lane >> 4) << 3))) * 272
        + (uint32_t)((lane >> 3) & 1) * 16;

    float s[8], sq[8];
    #pragma unroll
    for (int i = 0; i < 8; i++) { s[i] = 0.f; sq[i] = 0.f; }

    for (int z = 0; z < 2; z++) {
        // ---- stage B once per z: contiguous copy of pre-split padded image ----
        {
            const float4* wsrc = reinterpret_cast<const float4*>(g_wimg + (size_t)(layer * 2 + z) * 69632);
            float4* bdst = reinterpret_cast<float4*>(smc + SM_BHI);
            #pragma unroll
            for (int i = 0; i < 17; i++) bdst[tid + i * 256] = wsrc[tid + i * 256];
        }
        const float4* A4 = reinterpret_cast<const float4*>(z ? IN : A0);

        for (int tile = blockIdx.x; tile < NTILE; tile += GRID_G) {
            const int base = tile * 64;
            // ---- stage A: 64 rows fp32 (+affine z=1) -> bf16 hi/lo ----
            #pragma unroll
            for (int i = 0; i < 8; i++) {
                int qq = tid + i * 256;                // 0..2047
                int m = qq >> 5, c = qq & 31;
                int gr = base + m;
                float4 v = make_float4(0.f, 0.f, 0.f, 0.f);
                if (gr < NN) {
                    v = A4[gr * 32 + c];
                    if (z) {
                        float4 sc = reinterpret_cast<const float4*>(sbn)[c];
                        float4 sh = reinterpret_cast<const float4*>(sbn)[32 + c];
                        v.x = fmaf(v.x, sc.x, sh.x); v.y = fmaf(v.y, sc.y, sh.y);
                        v.z = fmaf(v.z, sc.z, sh.z); v.w = fmaf(v.w, sc.w, sh.w);
                    }
                }
                float h0 = __bfloat162float(__float2bfloat16(v.x));
                float h1 = __bfloat162float(__float2bfloat16(v.y));
                float h2 = __bfloat162float(__float2bfloat16(v.z));
                float h3 = __bfloat162float(__float2bfloat16(v.w));
                char* pa = smc + SM_AHI + m * 272 + c * 8;
                *reinterpret_cast<uint2*>(pa) = make_uint2(bfpair(h0, h1), bfpair(h2, h3));
                *reinterpret_cast<uint2*>(pa + 17408) =
                    make_uint2(bfpair(v.x - h0, v.y - h1), bfpair(v.z - h2, v.w - h3));
            }
            __syncthreads();

            float acc[2][4][4];
            #pragma unroll
            for (int f = 0; f < 2; f++)
                #pragma unroll
                for (int g = 0; g < 4; g++)
                    #pragma unroll
                    for (int e = 0; e < 4; e++) acc[f][g][e] = 0.f;

            #pragma unroll
            for (int ks = 0; ks < 8; ks++) {
                uint32_t ah[2][4], al[2][4], bh[2][4], bl[2][4];
                #pragma unroll
                for (int f = 0; f < 2; f++) {
                    uint32_t a = aBase + f * 4352 + ks * 32;
                    LDSM4(ah[f], a);
                    LDSM4(al[f], a + 17408);
                }
                #pragma unroll
                for (int gp = 0; gp < 2; gp++) {
                    uint32_t b = bBase + gp * 4352 + ks * 32;
                    LDSM4(bh[gp], b);
                    LDSM4(bl[gp], b + 34816);
                }
                #pragma unroll
                for (int f = 0; f < 2; f++)
                    #pragma unroll
                    for (int gp = 0; gp < 2; gp++)
                        #pragma unroll
                        for (int gs = 0; gs < 2; gs++) {
                            float* d = acc[f][2 * gp + gs];
                            MMA(d, ah[f][0], ah[f][1], ah[f][2], ah[f][3],
                                bh[gp][2 * gs], bh[gp][2 * gs + 1]);
                            MMA(d, ah[f][0], ah[f][1], ah[f][2], ah[f][3],
                                bl[gp][2 * gs], bl[gp][2 * gs + 1]);
                            MMA(d, al[f][0], al[f][1], al[f][2], al[f][3],
                                bh[gp][2 * gs], bh[gp][2 * gs + 1]);
                        }
            }

            // ---- epilogue ----
            if (z == 0) {
                #pragma unroll
                for (int f = 0; f < 2; f++)
                    #pragma unroll
                    for (int g = 0; g < 4; g++) {
                        int row = mw * 32 + f * 16 + r;
                        int col = nw * 32 + g * 8 + q2;
                        float b0 = sbias[col], b1 = sbias[col + 1];
                        int gr = base + row;
                        if (gr < NN)
                            *reinterpret_cast<float2*>(&OUT[gr * DD + col]) =
                                make_float2(relu(acc[f][g][0] + b0), relu(acc[f][g][1] + b1));
                        if (gr + 8 < NN)
                            *reinterpret_cast<float2*>(&OUT[(gr + 8) * DD + col]) =
                                make_float2(relu(acc[f][g][2] + b0), relu(acc[f][g][3] + b1));
                    }
            } else {
                #pragma unroll
                for (int f = 0; f < 2; f++)
                    #pragma unroll
                    for (int g = 0; g < 4; g++) {
                        int row = mw * 32 + f * 16 + r;
                        int col = nw * 32 + g * 8 + q2;
                        float rb0 = sbias[128 + col], rb1 = sbias[128 + col + 1];
                        int gr = base + row;
                        if (gr < NN) {
                            float2 c0 = *reinterpret_cast<const float2*>(&OUT[gr * DD + col]);
                            float h0 = c0.x + relu(acc[f][g][0] + rb0);
                            float h1 = c0.y + relu(acc[f][g][1] + rb1);
                            *reinterpret_cast<float2*>(&OUT[gr * DD + col]) = make_float2(h0, h1);
                            s[g * 2] += h0; s[g * 2 + 1] += h1;
                            sq[g * 2] += h0 * h0; sq[g * 2 + 1] += h1 * h1;
                        }
                        if (gr + 8 < NN) {
                            float2 c1 = *reinterpret_cast<const float2*>(&OUT[(gr + 8) * DD + col]);
                            float h2 = c1.x + relu(acc[f][g][2] + rb0);
                            float h3 = c1.y + relu(acc[f][g][3] + rb1);
                            *reinterpret_cast<float2*>(&OUT[(gr + 8) * DD + col]) = make_float2(h2, h3);
                            s[g * 2] += h2; s[g * 2 + 1] += h3;
                            sq[g * 2] += h2 * h2; sq[g * 2 + 1] += h3 * h3;
                        }
                    }
            }
            __syncthreads();
        }
    }

    // ---- stats -> g_stats[layer] ----
    #pragma unroll
    for (int i = 0; i < 8; i++) {
        #pragma unroll
        for (int off = 4; off < 32; off <<= 1) {
            s[i]  += __shfl_xor_sync(0xffffffffu, s[i], off);
            sq[i] += __shfl_xor_sync(0xffffffffu, sq[i], off);
        }
    }
    if (lane < 4) {
        #pragma unroll
        for (int g = 0; g < 4; g++) {
            int col = nw * 32 + g * 8 + lane * 2;
            ps[mw * 128 + col]     = s[g * 2];
            ps[mw * 128 + col + 1] = s[g * 2 + 1];
            qs[mw * 128 + col]     = sq[g * 2];
            qs[mw * 128 + col + 1] = sq[g * 2 + 1];
        }
    }
    __syncthreads();
    if (tid < 128) {
        atomicAdd(&g_stats[layer * 256 + tid], ps[tid] + ps[128 + tid]);
        atomicAdd(&g_stats[layer * 256 + 128 + tid], qs[tid] + qs[128 + tid]);
    }
}

// ---------------- final BN apply (layer-2 params computed locally) ----------------
__global__ void bn_apply_kernel(const float* __restrict__ H, float* __restrict__ outp,
                                const float* __restrict__ gam, const float* __restrict__ bet) {
    __shared__ float sbn[256];
    int tid = threadIdx.x;
    if (tid < 128) {
        float mu = g_stats[2 * 256 + tid] * (1.f / NN);
        float var = fmaxf(g_stats[2 * 256 + 128 + tid] * (1.f / NN) - mu * mu, 0.f);
        float inv = gam[2 * 128 + tid] * rsqrtf(var + BN_EPS_F);
        sbn[tid] = inv;
        sbn[128 + tid] = bet[2 * 128 + tid] - mu * inv;
    }
    __syncthreads();
    int idx = blockIdx.x * 256 + tid;
    int c = idx & 31;
    float4 h = reinterpret_cast<const float4*>(H)[idx];
    float4 sc = reinterpret_cast<const float4*>(sbn)[c];
    float4 sh = reinterpret_cast<const float4*>(sbn)[32 + c];
    float4 o;
    o.x = fmaf(h.x, sc.x, sh.x); o.y = fmaf(h.y, sc.y, sh.y);
    o.z = fmaf(h.z, sc.z, sh.z); o.w = fmaf(h.w, sc.w, sh.w);
    reinterpret_cast<float4*>(outp)[idx] = o;
}

// ---------------- launch ----------------
extern "C" void kernel_launch(void* const* d_in, const int* in_sizes, int n_in,
                              void* d_out, int out_size) {
    const int*   node_ids = (const int*)d_in[0];
    const int*   src      = (const int*)d_in[1];
    const int*   dst      = (const int*)d_in[2];
    const float* emb      = (const float*)d_in[3];
    const float* Ws       = (const float*)d_in[4];
    const float* bs       = (const float*)d_in[5];
    const float* Rws      = (const float*)d_in[6];
    const float* Rbs      = (const float*)d_in[7];
    const float* gam      = (const float*)d_in[8];
    const float* bet      = (const float*)d_in[9];
    float* outp = (float*)d_out;

    float *p_ha, *p_hb, *p_agg;
    cudaGetSymbolAddress((void**)&p_ha, g_ha);
    cudaGetSymbolAddress((void**)&p_hb, g_hb);
    cudaGetSymbolAddress((void**)&p_agg, g_agg);

    cudaFuncSetAttribute(gemm_kernel, cudaFuncAttributeMaxDynamicSharedMemorySize, TC_SMEM);

    const int NV4 = NN * DD / 4;
    prep0_kernel<<<NV4 / 256, 256>>>(node_ids, emb, Ws, Rws);
    count_deg_kernel<<<(NE + 255) / 256, 256>>>(src, dst);
    scanA_kernel<<<NBLK_SCAN, 256>>>();
    scanB_kernel<<<1, 256>>>();
    scanC_kernel<<<(NN + 255) / 256, 256>>>();
    fill_kernel<<<(NE + 255) / 256, 256>>>(src, dst);

    for (int l = 0; l < 3; l++) {
        const float* IN = (l & 1) ? p_hb : p_ha;
        float* OUT = (l & 1) ? p_ha : p_hb;
        gather_kernel<<<(NN + 7) / 8, 256>>>(IN, l, gam, bet);
        gemm_kernel<<<GRID_G, 256, TC_SMEM>>>(p_agg, IN, OUT, l,
                                              bs + l * DD, Rbs + l * DD, gam, bet);
    }
    bn_apply_kernel<<<NV4 / 256, 256>>>(p_hb, outp, gam, bet);
}

// round 16
// speedup vs baseline: 1.2256x; 1.0372x over previous
#include <cuda_runtime.h>
#include <cuda_bf16.h>
#include <cstdint>

#define NN 50000
#define NE 500000
#define DD 128
#define BN_EPS_F 1e-5f
#define NBLK_SCAN 196
#define NTILE 782              // ceil(50000/64)
#define GRID_G 296             // 148 SMs x 2 CTAs -> single wave

// smem layout (bytes): 64-row A tiles, full 128-row B tiles, stride 272 B (136 halfs)
#define SM_AHI 0
#define SM_ALO 17408
#define SM_BHI 34816
#define SM_BLO 69632
#define SM_BIAS 104448         // 256 floats: bias | rbias
#define SM_PS   105472         // 2 x 128 floats
#define SM_QS   106496         // 2 x 128 floats
#define TC_SMEM 107520

// ---------------- device scratch ----------------
__device__ __align__(16) float g_ha[NN * DD];
__device__ __align__(16) float g_hb[NN * DD];
__device__ __align__(16) float g_agg[NN * DD];
__device__ __align__(16) float g_bn[2 * DD];
__device__ float g_out_norm[NN];
__device__ float g_in_norm[NN];
__device__ int   g_deg[2 * NN];
__device__ int   g_rowptr[NN + 1];
__device__ int   g_fill[NN];
__device__ int   g_col[NE];
__device__ int   g_blk[256];
__device__ float g_stats[2 * DD];
// padded bf16 weight images: [layer][z][ hi 34816B | lo 34816B ], Bt[n][k] 136-half rows
__device__ __align__(16) char g_wimg[6 * 69632];

// ---------------- helpers ----------------
__device__ __forceinline__ float relu(float x) { return fmaxf(x, 0.f); }
__device__ __forceinline__ uint32_t bfpair(float x, float y) {
    __nv_bfloat162 t = __floats2bfloat162_rn(x, y);
    return *reinterpret_cast<uint32_t*>(&t);
}
__device__ __forceinline__ uint32_t smem_u32(const void* p) {
    uint32_t a;
    asm("{ .reg .u64 t; cvta.to.shared.u64 t, %1; cvt.u32.u64 %0, t; }" : "=r"(a) : "l"(p));
    return a;
}
#define MMA(d, a0, a1, a2, a3, b0, b1) \
    asm volatile("mma.sync.aligned.m16n8k16.row.col.f32.bf16.bf16.f32 " \
        "{%0,%1,%2,%3}, {%4,%5,%6,%7}, {%8,%9}, {%0,%1,%2,%3};" \
        : "+f"((d)[0]), "+f"((d)[1]), "+f"((d)[2]), "+f"((d)[3]) \
        : "r"(a0), "r"(a1), "r"(a2), "r"(a3), "r"(b0), "r"(b1))
#define LDSM4(r, a) \
    asm volatile("ldmatrix.sync.aligned.m8n8.x4.shared.b16 {%0,%1,%2,%3}, [%4];" \
        : "=r"((r)[0]), "=r"((r)[1]), "=r"((r)[2]), "=r"((r)[3]) : "r"(a))

// ---------------- prep kernels ----------------
// merged: zero deg/stats + identity BN + embed + weight split (all independent)
__global__ void prep0_kernel(const int* __restrict__ node_ids, const float* __restrict__ emb,
                             const float* __restrict__ Ws, const float* __restrict__ Rws) {
    int idx = blockIdx.x * 256 + threadIdx.x;
    if (idx < NN * 32) {               // embed
        int row = idx >> 5, c = idx & 31;
        reinterpret_cast<float4*>(g_ha)[idx] =
            reinterpret_cast<const float4*>(emb)[node_ids[row] * 32 + c];
    }
    if (idx < 2 * NN) g_deg[idx] = 0;
    if (idx < DD) { g_bn[idx] = 1.f; g_bn[DD + idx] = 0.f; g_stats[idx] = 0.f; g_stats[DD + idx] = 0.f; }
    if (idx < 6 * 128 * 136) {         // weight split + transpose + pad
        int kk = idx % 136, r = idx / 136;
        int n = r & 127; r >>= 7;
        int z = r & 1, l = r >> 1;
        float hi = 0.f, lo = 0.f;
        if (kk < 128) {
            float v = (z ? Rws : Ws)[l * 16384 + kk * 128 + n];
            __nv_bfloat16 h = __float2bfloat16(v);
            hi = __bfloat162float(h);
            lo = v - hi;
        }
        __nv_bfloat16* img = reinterpret_cast<__nv_bfloat16*>(g_wimg + (size_t)(l * 2 + z) * 69632);
        img[n * 136 + kk] = __float2bfloat16(hi);
        img[17408 + n * 136 + kk] = __float2bfloat16(lo);
    }
}
__global__ void count_deg_kernel(const int* __restrict__ src, const int* __restrict__ dst) {
    int e = blockIdx.x * 256 + threadIdx.x;
    if (e < NE) { atomicAdd(&g_deg[src[e]], 1); atomicAdd(&g_deg[NN + dst[e]], 1); }
}
// scanA + norms (both only need g_deg complete)
__global__ void scanA_kernel() {
    __shared__ int s[256];
    int t = threadIdx.x, b = blockIdx.x, i = b * 256 + t;
    int d = (i < NN) ? g_deg[NN + i] : 0;
    if (i < NN) {
        int d0 = g_deg[i];
        g_out_norm[i] = d0 > 0 ? rsqrtf((float)d0) : 0.f;
        g_in_norm[i]  = d > 0 ? rsqrtf((float)d) : 0.f;
    }
    s[t] = d; __syncthreads();
    #pragma unroll
    for (int off = 1; off < 256; off <<= 1) {
        int v = (t >= off) ? s[t - off] : 0; __syncthreads();
        s[t] += v; __syncthreads();
    }
    if (i < NN) g_rowptr[i] = s[t] - d;
    if (t == 255) g_blk[b] = s[255];
}
__global__ void scanB_kernel() {
    __shared__ int s[256];
    int t = threadIdx.x;
    int d = (t < NBLK_SCAN) ? g_blk[t] : 0;
    s[t] = d; __syncthreads();
    #pragma unroll
    for (int off = 1; off < 256; off <<= 1) {
        int v = (t >= off) ? s[t - off] : 0; __syncthreads();
        s[t] += v; __syncthreads();
    }
    g_blk[t] = s[t] - d;
}
__global__ void scanC_kernel() {
    int i = blockIdx.x * 256 + threadIdx.x;
    if (i < NN) { int rp = g_rowptr[i] + g_blk[i >> 8]; g_rowptr[i] = rp; g_fill[i] = rp; }
    if (i == 0) g_rowptr[NN] = NE;
}
__global__ void fill_kernel(const int* __restrict__ src, const int* __restrict__ dst) {
    int e = blockIdx.x * 256 + threadIdx.x;
    if (e < NE) g_col[atomicAdd(&g_fill[dst[e]], 1)] = src[e];
}

// ---------------- gather: MLP-8 neighbor batching, BN affine from g_bn ----------------
__global__ void gather_kernel(const float* __restrict__ IN) {
    int nid = blockIdx.x * 8 + (threadIdx.x >> 5);
    if (nid >= NN) return;
    int lane = threadIdx.x & 31;
    int j = g_rowptr[nid], end = g_rowptr[nid + 1];
    const float4* x4 = reinterpret_cast<const float4*>(IN);
    float4 sc = reinterpret_cast<const float4*>(g_bn)[lane];
    float4 sh = reinterpret_cast<const float4*>(g_bn)[32 + lane];
    float4 acc = make_float4(0.f, 0.f, 0.f, 0.f);
    float nsum = 0.f;
    for (; j + 8 <= end; j += 8) {
        int ss[8]; float nn[8]; float4 vv[8];
        #pragma unroll
        for (int q = 0; q < 8; q++) ss[q] = g_col[j + q];
        #pragma unroll
        for (int q = 0; q < 8; q++) nn[q] = g_out_norm[ss[q]];
        #pragma unroll
        for (int q = 0; q < 8; q++) vv[q] = x4[ss[q] * 32 + lane];
        #pragma unroll
        for (int q = 0; q < 8; q++) {
            acc.x = fmaf(nn[q], vv[q].x, acc.x);
            acc.y = fmaf(nn[q], vv[q].y, acc.y);
            acc.z = fmaf(nn[q], vv[q].z, acc.z);
            acc.w = fmaf(nn[q], vv[q].w, acc.w);
            nsum += nn[q];
        }
    }
    for (; j + 4 <= end; j += 4) {
        int s0 = g_col[j], s1 = g_col[j + 1], s2 = g_col[j + 2], s3 = g_col[j + 3];
        float n0 = g_out_norm[s0], n1 = g_out_norm[s1], n2 = g_out_norm[s2], n3 = g_out_norm[s3];
        float4 v0 = x4[s0 * 32 + lane], v1 = x4[s1 * 32 + lane];
        float4 v2 = x4[s2 * 32 + lane], v3 = x4[s3 * 32 + lane];
        acc.x += n0 * v0.x + n1 * v1.x + n2 * v2.x + n3 * v3.x;
        acc.y += n0 * v0.y + n1 * v1.y + n2 * v2.y + n3 * v3.y;
        acc.z += n0 * v0.z + n1 * v1.z + n2 * v2.z + n3 * v3.z;
        acc.w += n0 * v0.w + n1 * v1.w + n2 * v2.w + n3 * v3.w;
        nsum += n0 + n1 + n2 + n3;
    }
    for (; j < end; j++) {
        int s = g_col[j]; float on = g_out_norm[s];
        float4 v = x4[s * 32 + lane];
        acc.x = fmaf(on, v.x, acc.x); acc.y = fmaf(on, v.y, acc.y);
        acc.z = fmaf(on, v.z, acc.z); acc.w = fmaf(on, v.w, acc.w);
        nsum += on;
    }
    float inr = g_in_norm[nid];
    float4 o;
    o.x = inr * fmaf(sc.x, acc.x, sh.x * nsum);
    o.y = inr * fmaf(sc.y, acc.y, sh.y * nsum);
    o.z = inr * fmaf(sc.z, acc.z, sh.z * nsum);
    o.w = inr * fmaf(sc.w, acc.w, sh.w * nsum);
    reinterpret_cast<float4*>(g_agg)[nid * 32 + lane] = o;
}

// ---------------- HMMA dual GEMM: 1-wave grid, multi-tile per B load ----------------
__global__ void __launch_bounds__(256, 2)
gemm_kernel(const float* __restrict__ A0, const float* __restrict__ IN,
            float* __restrict__ OUT, int layer,
            const float* __restrict__ bvec, const float* __restrict__ rbvec,
            int do_stats) {
    extern __shared__ char smc[];
    const uint32_t ub = smem_u32(smc);
    float* sbias = reinterpret_cast<float*>(smc + SM_BIAS);
    float* ps    = reinterpret_cast<float*>(smc + SM_PS);
    float* qs    = reinterpret_cast<float*>(smc + SM_QS);

    const int tid = threadIdx.x, lane = tid & 31, wid = tid >> 5;
    const int mw = wid & 1, nw = wid >> 1;       // 2 row-warps x 4 col-warps
    const int r = lane >> 2, q2 = (lane & 3) * 2;

    if (tid < 128) { sbias[tid] = bvec[tid]; sbias[128 + tid] = rbvec[tid]; }

    const uint32_t aBase = ub + SM_AHI
        + (uint32_t)(mw * 32 + (lane & 15)) * 272 + (uint32_t)(lane >> 4) * 16;
    const uint32_t bBase = ub + SM_BHI
        + (uint32_t)(nw * 32 + ((lane & 7) | ((lane >> 4) << 3))) * 272
        + (uint32_t)((lane >> 3) & 1) * 16;

    float s[8], sq[8];
    #pragma unroll
    for (int i = 0; i < 8; i++) { s[i] = 0.f; sq[i] = 0.f; }

    const float4* BN4 = reinterpret_cast<const float4*>(g_bn);

    for (int z = 0; z < 2; z++) {
        // ---- stage B once per z: contiguous copy of pre-split padded image ----
        {
            const float4* wsrc = reinterpret_cast<const float4*>(g_wimg + (size_t)(layer * 2 + z) * 69632);
            float4* bdst = reinterpret_cast<float4*>(smc + SM_BHI);
            #pragma unroll
            for (int i = 0; i < 17; i++) bdst[tid + i * 256] = wsrc[tid + i * 256];
        }
        const float4* A4 = reinterpret_cast<const float4*>(z ? IN : A0);

        for (int tile = blockIdx.x; tile < NTILE; tile += GRID_G) {
            const int base = tile * 64;
            // ---- stage A: 64 rows fp32 (+affine z=1) -> bf16 hi/lo ----
            #pragma unroll
            for (int i = 0; i < 8; i++) {
                int qq = tid + i * 256;                // 0..2047
                int m = qq >> 5, c = qq & 31;
                int gr = base + m;
                float4 v = make_float4(0.f, 0.f, 0.f, 0.f);
                if (gr < NN) {
                    v = A4[gr * 32 + c];
                    if (z) {
                        float4 sc = BN4[c], sh = BN4[32 + c];
                        v.x = fmaf(v.x, sc.x, sh.x); v.y = fmaf(v.y, sc.y, sh.y);
                        v.z = fmaf(v.z, sc.z, sh.z); v.w = fmaf(v.w, sc.w, sh.w);
                    }
                }
                float h0 = __bfloat162float(__float2bfloat16(v.x));
                float h1 = __bfloat162float(__float2bfloat16(v.y));
                float h2 = __bfloat162float(__float2bfloat16(v.z));
                float h3 = __bfloat162float(__float2bfloat16(v.w));
                char* pa = smc + SM_AHI + m * 272 + c * 8;
                *reinterpret_cast<uint2*>(pa) = make_uint2(bfpair(h0, h1), bfpair(h2, h3));
                *reinterpret_cast<uint2*>(pa + 17408) =
                    make_uint2(bfpair(v.x - h0, v.y - h1), bfpair(v.z - h2, v.w - h3));
            }
            __syncthreads();

            float acc[2][4][4];
            #pragma unroll
            for (int f = 0; f < 2; f++)
                #pragma unroll
                for (int g = 0; g < 4; g++)
                    #pragma unroll
                    for (int e = 0; e < 4; e++) acc[f][g][e] = 0.f;

            #pragma unroll
            for (int ks = 0; ks < 8; ks++) {
                uint32_t ah[2][4], al[2][4], bh[2][4], bl[2][4];
                #pragma unroll
                for (int f = 0; f < 2; f++) {
                    uint32_t a = aBase + f * 4352 + ks * 32;
                    LDSM4(ah[f], a);
                    LDSM4(al[f], a + 17408);
                }
                #pragma unroll
                for (int gp = 0; gp < 2; gp++) {
                    uint32_t b = bBase + gp * 4352 + ks * 32;
                    LDSM4(bh[gp], b);
                    LDSM4(bl[gp], b + 34816);
                }
                #pragma unroll
                for (int f = 0; f < 2; f++)
                    #pragma unroll
                    for (int gp = 0; gp < 2; gp++)
                        #pragma unroll
                        for (int gs = 0; gs < 2; gs++) {
                            float* d = acc[f][2 * gp + gs];
                            MMA(d, ah[f][0], ah[f][1], ah[f][2], ah[f][3],
                                bh[gp][2 * gs], bh[gp][2 * gs + 1]);
                            MMA(d, ah[f][0], ah[f][1], ah[f][2], ah[f][3],
                                bl[gp][2 * gs], bl[gp][2 * gs + 1]);
                            MMA(d, al[f][0], al[f][1], al[f][2], al[f][3],
                                bh[gp][2 * gs], bh[gp][2 * gs + 1]);
                        }
            }

            // ---- epilogue ----
            if (z == 0) {
                #pragma unroll
                for (int f = 0; f < 2; f++)
                    #pragma unroll
                    for (int g = 0; g < 4; g++) {
                        int row = mw * 32 + f * 16 + r;
                        int col = nw * 32 + g * 8 + q2;
                        float b0 = sbias[col], b1 = sbias[col + 1];
                        int gr = base + row;
                        if (gr < NN)
                            *reinterpret_cast<float2*>(&OUT[gr * DD + col]) =
                                make_float2(relu(acc[f][g][0] + b0), relu(acc[f][g][1] + b1));
                        if (gr + 8 < NN)
                            *reinterpret_cast<float2*>(&OUT[(gr + 8) * DD + col]) =
                                make_float2(relu(acc[f][g][2] + b0), relu(acc[f][g][3] + b1));
                    }
            } else {
                #pragma unroll
                for (int f = 0; f < 2; f++)
                    #pragma unroll
                    for (int g = 0; g < 4; g++) {
                        int row = mw * 32 + f * 16 + r;
                        int col = nw * 32 + g * 8 + q2;
                        float rb0 = sbias[128 + col], rb1 = sbias[128 + col + 1];
                        int gr = base + row;
                        if (gr < NN) {
                            float2 c0 = *reinterpret_cast<const float2*>(&OUT[gr * DD + col]);
                            float h0 = c0.x + relu(acc[f][g][0] + rb0);
                            float h1 = c0.y + relu(acc[f][g][1] + rb1);
                            *reinterpret_cast<float2*>(&OUT[gr * DD + col]) = make_float2(h0, h1);
                            s[g * 2] += h0; s[g * 2 + 1] += h1;
                            sq[g * 2] += h0 * h0; sq[g * 2 + 1] += h1 * h1;
                        }
                        if (gr + 8 < NN) {
                            float2 c1 = *reinterpret_cast<const float2*>(&OUT[(gr + 8) * DD + col]);
                            float h2 = c1.x + relu(acc[f][g][2] + rb0);
                            float h3 = c1.y + relu(acc[f][g][3] + rb1);
                            *reinterpret_cast<float2*>(&OUT[(gr + 8) * DD + col]) = make_float2(h2, h3);
                            s[g * 2] += h2; s[g * 2 + 1] += h3;
                            sq[g * 2] += h2 * h2; sq[g * 2 + 1] += h3 * h3;
                        }
                    }
            }
            __syncthreads();
        }
    }

    if (do_stats) {
        #pragma unroll
        for (int i = 0; i < 8; i++) {
            #pragma unroll
            for (int off = 4; off < 32; off <<= 1) {
                s[i]  += __shfl_xor_sync(0xffffffffu, s[i], off);
                sq[i] += __shfl_xor_sync(0xffffffffu, sq[i], off);
            }
        }
        if (lane < 4) {
            #pragma unroll
            for (int g = 0; g < 4; g++) {
                int col = nw * 32 + g * 8 + lane * 2;
                ps[mw * 128 + col]     = s[g * 2];
                ps[mw * 128 + col + 1] = s[g * 2 + 1];
                qs[mw * 128 + col]     = sq[g * 2];
                qs[mw * 128 + col + 1] = sq[g * 2 + 1];
            }
        }
        __syncthreads();
        if (tid < 128) {
            atomicAdd(&g_stats[tid], ps[tid] + ps[128 + tid]);
            atomicAdd(&g_stats[DD + tid], qs[tid] + qs[128 + tid]);
        }
    }
}

// ---------------- batchnorm ----------------
__global__ void bn_stats_kernel(const float* __restrict__ gamma, const float* __restrict__ beta) {
    int c = threadIdx.x;
    float mu = g_stats[c] * (1.f / NN);
    float var = fmaxf(g_stats[DD + c] * (1.f / NN) - mu * mu, 0.f);
    float inv = gamma[c] * rsqrtf(var + BN_EPS_F);
    g_bn[c] = inv;
    g_bn[DD + c] = beta[c] - mu * inv;
    g_stats[c] = 0.f; g_stats[DD + c] = 0.f;
}

__global__ void bn_apply_kernel(const float* __restrict__ H, float* __restrict__ outp) {
    int idx = blockIdx.x * 256 + threadIdx.x;
    int c = (idx & 31) << 2;
    float4 h = reinterpret_cast<const float4*>(H)[idx];
    float4 o;
    o.x = h.x * g_bn[c + 0] + g_bn[DD + c + 0];
    o.y = h.y * g_bn[c + 1] + g_bn[DD + c + 1];
    o.z = h.z * g_bn[c + 2] + g_bn[DD + c + 2];
    o.w = h.w * g_bn[c + 3] + g_bn[DD + c + 3];
    reinterpret_cast<float4*>(outp)[idx] = o;
}

// ---------------- launch ----------------
extern "C" void kernel_launch(void* const* d_in, const int* in_sizes, int n_in,
                              void* d_out, int out_size) {
    const int*   node_ids = (const int*)d_in[0];
    const int*   src      = (const int*)d_in[1];
    const int*   dst      = (const int*)d_in[2];
    const float* emb      = (const float*)d_in[3];
    const float* Ws       = (const float*)d_in[4];
    const float* bs       = (const float*)d_in[5];
    const float* Rws      = (const float*)d_in[6];
    const float* Rbs      = (const float*)d_in[7];
    const float* gam      = (const float*)d_in[8];
    const float* bet      = (const float*)d_in[9];
    float* outp = (float*)d_out;

    float *p_ha, *p_hb, *p_agg;
    cudaGetSymbolAddress((void**)&p_ha, g_ha);
    cudaGetSymbolAddress((void**)&p_hb, g_hb);
    cudaGetSymbolAddress((void**)&p_agg, g_agg);

    cudaFuncSetAttribute(gemm_kernel, cudaFuncAttributeMaxDynamicSharedMemorySize, TC_SMEM);

    const int NV4 = NN * DD / 4;
    prep0_kernel<<<NV4 / 256, 256>>>(node_ids, emb, Ws, Rws);
    count_deg_kernel<<<(NE + 255) / 256, 256>>>(src, dst);
    scanA_kernel<<<NBLK_SCAN, 256>>>();
    scanB_kernel<<<1, 256>>>();
    scanC_kernel<<<(NN + 255) / 256, 256>>>();
    fill_kernel<<<(NE + 255) / 256, 256>>>(src, dst);

    for (int l = 0; l < 3; l++) {
        const float* IN = (l & 1) ? p_hb : p_ha;
        float* OUT = (l & 1) ? p_ha : p_hb;
        gather_kernel<<<(NN + 7) / 8, 256>>>(IN);
        gemm_kernel<<<GRID_G, 256, TC_SMEM>>>(p_agg, IN, OUT, l,
                                              bs + l * DD, Rbs + l * DD, 1);
        bn_stats_kernel<<<1, DD>>>(gam + l * DD, bet + l * DD);
    }
    bn_apply_kernel<<<NV4 / 256, 256>>>(p_hb, outp);
}